// round 2
// baseline (speedup 1.0000x reference)
#include <cuda_runtime.h>
#include <cuda_bf16.h>
#include <math.h>

// Problem constants
#define NB     32
#define NPOLY  256
#define VPP    64
#define LDIM   32
#define V_TOT  (1 + NPOLY * VPP)   // 16385 rows per batch in `data`

// Scratch (device globals: no allocations allowed)
__device__ float g_P2[NB * NPOLY * 128];   // agg2 per (b, poly): P = [agg2, agg2]
__device__ float g_Wq[128 * 256];          // folded Wq[:128] + Wq[128:]
__device__ float g_Wk[128 * 256];
__device__ float g_Wv[128 * 256];

// ---------------------------------------------------------------------------
// Stage 1: per (b, poly) block — 3 x (GEMM + LayerNorm + ReLU + column max)
// Exploits:  x = concat([h, broadcast(agg)])  =>  per-row GEMM uses only the
// top CIN rows of W; the agg part folds into a per-block "shared" term.
// Only agg2 (128 floats) is emitted: P = concat([agg2, agg2]).
// ---------------------------------------------------------------------------
template<int CIN, int COUT, bool FIRST, bool LAST>
__device__ __forceinline__ void layer(
    const float* __restrict__ in_s,   // 64 x CIN (smem)
    float*       __restrict__ out_s,  // 64 x COUT (smem) or unused if LAST
    float*       __restrict__ Ws,     // smem weight buffer (CIN x COUT)
    const float* __restrict__ W,      // global weights ((CIN or 2*CIN) x COUT)
    const float* __restrict__ bias,
    const float* __restrict__ g,
    const float* __restrict__ beta,
    const float* __restrict__ aggp,   // previous agg (CIN) or unused if FIRST
    float*       __restrict__ shs,    // smem shared-term (COUT)
    int*         __restrict__ aggc,   // smem column max (COUT), float bits as int
    int tid)
{
    constexpr int PC = COUT / 32;     // columns per lane
    const int warp = tid >> 5, lane = tid & 31;

    // Varying-part weights W[0:CIN][0:COUT] are the FIRST CIN*COUT floats (contiguous).
    for (int i = tid; i < CIN * COUT; i += 256) Ws[i] = W[i];

    // Shared term: bias + agg_prev @ W[CIN:2*CIN]
    for (int c = tid; c < COUT; c += 256) {
        float s = bias[c];
        if (!FIRST) {
            #pragma unroll 4
            for (int k = 0; k < CIN; k++)
                s = fmaf(aggp[k], W[(CIN + k) * COUT + c], s);
        }
        shs[c]  = s;
        aggc[c] = 0;   // relu output >= 0: float bits monotone as int
    }
    __syncthreads();

    float gr[PC], br[PC], mx[PC];
    #pragma unroll
    for (int j = 0; j < PC; j++) {
        const int c = lane * PC + j;
        gr[j] = g[c]; br[j] = beta[c]; mx[j] = 0.f;
    }

    // Each warp: 8 rows, register-blocked 4 rows at a time (reuses W loads).
    for (int rg = 0; rg < 2; rg++) {
        const int rbase = warp * 8 + rg * 4;
        float acc[4][PC];
        #pragma unroll
        for (int rr = 0; rr < 4; rr++)
            #pragma unroll
            for (int j = 0; j < PC; j++) acc[rr][j] = shs[lane * PC + j];

        for (int k = 0; k < CIN; k += 4) {
            float4 a[4];
            #pragma unroll
            for (int rr = 0; rr < 4; rr++)
                a[rr] = *(const float4*)(in_s + (rbase + rr) * CIN + k);
            #pragma unroll
            for (int kk = 0; kk < 4; kk++) {
                const float* w = Ws + (k + kk) * COUT + lane * PC;
                float wv[PC];
                #pragma unroll
                for (int j = 0; j < PC; j++) wv[j] = w[j];
                #pragma unroll
                for (int rr = 0; rr < 4; rr++) {
                    const float av = (&a[rr].x)[kk];
                    #pragma unroll
                    for (int j = 0; j < PC; j++)
                        acc[rr][j] = fmaf(av, wv[j], acc[rr][j]);
                }
            }
        }

        // Per-row LayerNorm + ReLU + running column max
        #pragma unroll
        for (int rr = 0; rr < 4; rr++) {
            float sum = 0.f, sq = 0.f;
            #pragma unroll
            for (int j = 0; j < PC; j++) { sum += acc[rr][j]; sq += acc[rr][j] * acc[rr][j]; }
            #pragma unroll
            for (int o = 16; o > 0; o >>= 1) {
                sum += __shfl_xor_sync(0xffffffffu, sum, o);
                sq  += __shfl_xor_sync(0xffffffffu, sq,  o);
            }
            const float mu  = sum * (1.0f / COUT);
            const float var = fmaxf(sq * (1.0f / COUT) - mu * mu, 0.f);
            const float inv = rsqrtf(var + 1e-5f);
            #pragma unroll
            for (int j = 0; j < PC; j++) {
                float v = fmaxf(fmaf(gr[j] * (acc[rr][j] - mu), inv, br[j]), 0.f);
                if (!LAST) out_s[(rbase + rr) * COUT + lane * PC + j] = v;
                mx[j] = fmaxf(mx[j], v);
            }
        }
    }
    #pragma unroll
    for (int j = 0; j < PC; j++)
        atomicMax(&aggc[lane * PC + j], __float_as_int(mx[j]));
    __syncthreads();
}

__global__ void __launch_bounds__(256) stage1_kernel(
    const float* __restrict__ data,
    const float* __restrict__ W0, const float* __restrict__ b0,
    const float* __restrict__ g0, const float* __restrict__ be0,
    const float* __restrict__ W1, const float* __restrict__ b1,
    const float* __restrict__ g1, const float* __restrict__ be1,
    const float* __restrict__ W2, const float* __restrict__ b2,
    const float* __restrict__ g2, const float* __restrict__ be2)
{
    extern __shared__ float smem[];
    float* bufA = smem;                  // 64*64  (x as 64x32, later h1 64x64)
    float* bufB = bufA + 64 * 64;        // 64*32  (h0)
    float* Ws   = bufB + 64 * 32;        // 64*128 (weight tile)
    float* aggp = Ws + 64 * 128;         // 128
    float* shs  = aggp + 128;            // 128
    int*   aggc = (int*)(shs + 128);     // 128

    const int tid = threadIdx.x;
    const int blk = blockIdx.x;          // b*NPOLY + p
    const int b = blk >> 8, p = blk & 255;

    // Load x tile (64 x 32), zero channel 31 (vecs[:, :, -1] = 0)
    const float* src = data + (size_t)b * V_TOT * LDIM + LDIM + (size_t)p * VPP * LDIM;
    for (int i = tid; i < 64 * 32; i += 256) {
        float v = src[i];
        if ((i & 31) == 31) v = 0.f;
        bufA[i] = v;
    }
    __syncthreads();

    layer<32, 32,  true,  false>(bufA, bufB, Ws, W0, b0, g0, be0, nullptr, shs, aggc, tid);
    for (int c = tid; c < 32; c += 256) aggp[c] = __int_as_float(aggc[c]);
    __syncthreads();

    layer<32, 64,  false, false>(bufB, bufA, Ws, W1, b1, g1, be1, aggp, shs, aggc, tid);
    for (int c = tid; c < 64; c += 256) aggp[c] = __int_as_float(aggc[c]);
    __syncthreads();

    layer<64, 128, false, true >(bufA, nullptr, Ws, W2, b2, g2, be2, aggp, shs, aggc, tid);

    float* P2 = g_P2 + (size_t)blk * 128;
    for (int c = tid; c < 128; c += 256) P2[c] = __int_as_float(aggc[c]);
}

// ---------------------------------------------------------------------------
// Fold Wq/Wk/Wv:  W_eff[j][c] = W[j][c] + W[j+128][c]   (P = [agg2, agg2])
// ---------------------------------------------------------------------------
__global__ void __launch_bounds__(256) fold_kernel(
    const float* __restrict__ Wq, const float* __restrict__ Wk,
    const float* __restrict__ Wv)
{
    const int i = blockIdx.x * 256 + threadIdx.x;
    if (i >= 128 * 256) return;
    const int j = i >> 8, c = i & 255;
    g_Wq[i] = Wq[j * 256 + c] + Wq[(j + 128) * 256 + c];
    g_Wk[i] = Wk[j * 256 + c] + Wk[(j + 128) * 256 + c];
    g_Wv[i] = Wv[j * 256 + c] + Wv[(j + 128) * 256 + c];
}

// ---------------------------------------------------------------------------
// Stage 2: attention, fully algebraically reduced. One block per batch.
//   q = P2[b, aid] @ Wq_eff + bq
//   t = Wk_eff @ q            (scores = P2 . t / 16 + const; const cancels)
//   att = softmax(scores)
//   out = (sum_p att_p * P2[b,p]) @ Wv_eff + bv
// ---------------------------------------------------------------------------
__global__ void __launch_bounds__(256) attn_kernel(
    const float* __restrict__ data,
    const float* __restrict__ bq, const float* __restrict__ bk_,
    const float* __restrict__ bv, float* __restrict__ out)
{
    __shared__ float ps[128], qs[256], ts[128], att[256], pbar[128], red[256];
    const int b = blockIdx.x, tid = threadIdx.x;

    const int aid = (int)data[(size_t)b * V_TOT * LDIM];   // data[b][0][0]
    if (tid < 128) ps[tid] = g_P2[((size_t)b * NPOLY + aid) * 128 + tid];
    __syncthreads();

    // q[c]
    {
        float acc = bq[tid];
        #pragma unroll 4
        for (int j = 0; j < 128; j++) acc = fmaf(ps[j], g_Wq[j * 256 + tid], acc);
        qs[tid] = acc;
    }
    __syncthreads();

    // t[j] = sum_c Wk_eff[j][c] * q[c]
    if (tid < 128) {
        float acc = 0.f;
        #pragma unroll 4
        for (int c = 0; c < 256; c++) acc = fmaf(g_Wk[tid * 256 + c], qs[c], acc);
        ts[tid] = acc;
    }
    __syncthreads();

    // scores (per poly p = tid)
    float s = 0.f;
    {
        const float4* Pp = (const float4*)(g_P2 + ((size_t)b * NPOLY + tid) * 128);
        #pragma unroll 8
        for (int j = 0; j < 32; j++) {
            float4 pv = Pp[j];
            s = fmaf(pv.x, ts[4 * j + 0], s);
            s = fmaf(pv.y, ts[4 * j + 1], s);
            s = fmaf(pv.z, ts[4 * j + 2], s);
            s = fmaf(pv.w, ts[4 * j + 3], s);
        }
        s *= 0.0625f;   // 1/sqrt(256)
    }
    // softmax over 256
    red[tid] = s; __syncthreads();
    for (int o = 128; o > 0; o >>= 1) {
        if (tid < o) red[tid] = fmaxf(red[tid], red[tid + o]);
        __syncthreads();
    }
    const float m = red[0]; __syncthreads();
    const float e = expf(s - m);
    red[tid] = e; __syncthreads();
    for (int o = 128; o > 0; o >>= 1) {
        if (tid < o) red[tid] += red[tid + o];
        __syncthreads();
    }
    att[tid] = e / red[0];
    __syncthreads();

    // pbar[j] = sum_p att[p] * P2[b,p,j]   (coalesced across tid=j)
    if (tid < 128) {
        float acc = 0.f;
        const float* Pb = g_P2 + (size_t)b * NPOLY * 128;
        for (int p = 0; p < 256; p++) acc = fmaf(att[p], Pb[p * 128 + tid], acc);
        pbar[tid] = acc;
    }
    __syncthreads();

    // out[c]
    {
        float acc = bv[tid];
        #pragma unroll 4
        for (int j = 0; j < 128; j++) acc = fmaf(pbar[j], g_Wv[j * 256 + tid], acc);
        out[b * 256 + tid] = acc;
    }
}

// ---------------------------------------------------------------------------
extern "C" void kernel_launch(void* const* d_in, const int* in_sizes, int n_in,
                              void* d_out, int out_size)
{
    const float* data = (const float*)d_in[0];
    const float* W0 = (const float*)d_in[1];
    const float* b0 = (const float*)d_in[2];
    const float* g0 = (const float*)d_in[3];
    const float* be0= (const float*)d_in[4];
    const float* W1 = (const float*)d_in[5];
    const float* b1 = (const float*)d_in[6];
    const float* g1 = (const float*)d_in[7];
    const float* be1= (const float*)d_in[8];
    const float* W2 = (const float*)d_in[9];
    const float* b2 = (const float*)d_in[10];
    const float* g2 = (const float*)d_in[11];
    const float* be2= (const float*)d_in[12];
    const float* Wq = (const float*)d_in[13];
    const float* bq = (const float*)d_in[14];
    const float* Wk = (const float*)d_in[15];
    const float* bk = (const float*)d_in[16];
    const float* Wv = (const float*)d_in[17];
    const float* bv = (const float*)d_in[18];
    float* out = (float*)d_out;

    const int smem_bytes = (64*64 + 64*32 + 64*128 + 128 + 128 + 128) * (int)sizeof(float);
    cudaFuncSetAttribute(stage1_kernel,
                         cudaFuncAttributeMaxDynamicSharedMemorySize, smem_bytes);

    stage1_kernel<<<NB * NPOLY, 256, smem_bytes>>>(
        data, W0, b0, g0, be0, W1, b1, g1, be1, W2, b2, g2, be2);
    fold_kernel<<<(128 * 256 + 255) / 256, 256>>>(Wq, Wk, Wv);
    attn_kernel<<<NB, 256>>>(data, bq, bk, bv, out);
}

// round 5
// speedup vs baseline: 1.1911x; 1.1911x over previous
#include <cuda_runtime.h>
#include <cuda_bf16.h>
#include <math.h>

// Problem constants
#define NB     32
#define NPOLY  256
#define VPP    64
#define LDIM   32
#define V_TOT  (1 + NPOLY * VPP)   // 16385 rows per batch in `data`

// Scratch (device globals: no allocations allowed)
__device__ float g_P2[NB * NPOLY * 128];   // agg2 per (b, poly): P = [agg2, agg2]
__device__ float g_Wq[128 * 256];          // folded Wq[:128] + Wq[128:]
__device__ float g_Wk[128 * 256];
__device__ float g_Wv[128 * 256];

// ---- packed f32x2 helpers (sm_103a dual-fp32 pipe; PTX-only) -------------
__device__ __forceinline__ unsigned long long pack2(float x, float y) {
    unsigned long long r;
    asm("mov.b64 %0, {%1, %2};" : "=l"(r) : "f"(x), "f"(y));
    return r;
}
__device__ __forceinline__ unsigned long long ffma2(unsigned long long a,
                                                    unsigned long long b,
                                                    unsigned long long c) {
    unsigned long long d;
    asm("fma.rn.f32x2 %0, %1, %2, %3;" : "=l"(d) : "l"(a), "l"(b), "l"(c));
    return d;
}
__device__ __forceinline__ float2 unpack2(unsigned long long v) {
    float2 f;
    asm("mov.b64 {%0, %1}, %2;" : "=f"(f.x), "=f"(f.y) : "l"(v));
    return f;
}

// ---------------------------------------------------------------------------
// Stage 1: per (b, poly) block — 3 x (GEMM + LayerNorm + ReLU + column max)
// x = concat([h, broadcast(agg)]) => per-row GEMM uses only the top CIN rows
// of W; the agg part folds into a per-block shared term. Only agg2 (128) is
// emitted: P = concat([agg2, agg2]).
// Inner product uses fma.rn.f32x2: 2 fp32 MACs per issue.
// ---------------------------------------------------------------------------
template<int CIN, int COUT, bool FIRST, bool LAST>
__device__ __forceinline__ void layer(
    const float* __restrict__ in_s,   // 64 x CIN (smem)
    float*       __restrict__ out_s,  // 64 x COUT (smem) or unused if LAST
    float*       __restrict__ Ws,     // smem weight buffer (CIN x COUT floats)
    const float* __restrict__ W,      // global weights ((CIN or 2*CIN) x COUT)
    const float* __restrict__ bias,
    const float* __restrict__ g,
    const float* __restrict__ beta,
    const float* __restrict__ aggp,   // previous agg (CIN) or unused if FIRST
    float*       __restrict__ shs,    // smem shared-term (COUT)
    int*         __restrict__ aggc,   // smem column max (COUT), float bits as int
    int tid)
{
    constexpr int PC = COUT / 32;     // columns per lane (1, 2, or 4)
    const int warp = tid >> 5, lane = tid & 31;

    // Stage varying-part weights W[0:CIN][0:COUT] (contiguous, vectorized)
    for (int i = tid; i < CIN * COUT / 4; i += 256)
        ((float4*)Ws)[i] = ((const float4*)W)[i];

    // Shared term: bias + agg_prev @ W[CIN:2*CIN]
    for (int c = tid; c < COUT; c += 256) {
        float s = bias[c];
        if (!FIRST) {
            #pragma unroll 4
            for (int k = 0; k < CIN; k++)
                s = fmaf(aggp[k], W[(CIN + k) * COUT + c], s);
        }
        shs[c]  = s;
        aggc[c] = 0;   // relu output >= 0: float bits monotone as int
    }
    __syncthreads();

    float gr[PC], br[PC], mx[PC];
    #pragma unroll
    for (int j = 0; j < PC; j++) {
        const int c = lane * PC + j;
        gr[j] = g[c]; br[j] = beta[c]; mx[j] = 0.f;
    }

    // Each warp: 8 rows, register-blocked 4 rows (weights reused across rows).
    for (int rg = 0; rg < 2; rg++) {
        const int rbase = warp * 8 + rg * 4;
        float vals[4][PC];   // post-GEMM values (filled below)

        if constexpr (PC >= 2) {
            constexpr int NP = PC / 2;
            unsigned long long acc[4][NP];
            #pragma unroll
            for (int rr = 0; rr < 4; rr++)
                #pragma unroll
                for (int j = 0; j < NP; j++)
                    acc[rr][j] = *(const unsigned long long*)(shs + lane * PC + 2 * j);

            for (int k = 0; k < CIN; k += 4) {
                float4 a[4];
                #pragma unroll
                for (int rr = 0; rr < 4; rr++)
                    a[rr] = *(const float4*)(in_s + (rbase + rr) * CIN + k);
                #pragma unroll
                for (int kk = 0; kk < 4; kk++) {
                    const unsigned long long* wp =
                        (const unsigned long long*)(Ws + (k + kk) * COUT + lane * PC);
                    unsigned long long w[NP];
                    #pragma unroll
                    for (int j = 0; j < NP; j++) w[j] = wp[j];
                    #pragma unroll
                    for (int rr = 0; rr < 4; rr++) {
                        const float av = (&a[rr].x)[kk];
                        const unsigned long long ap = pack2(av, av);
                        #pragma unroll
                        for (int j = 0; j < NP; j++)
                            acc[rr][j] = ffma2(ap, w[j], acc[rr][j]);
                    }
                }
            }
            #pragma unroll
            for (int rr = 0; rr < 4; rr++)
                #pragma unroll
                for (int j = 0; j < NP; j++) {
                    float2 f = unpack2(acc[rr][j]);
                    vals[rr][2 * j] = f.x; vals[rr][2 * j + 1] = f.y;
                }
        } else {
            float acc[4];
            #pragma unroll
            for (int rr = 0; rr < 4; rr++) acc[rr] = shs[lane];
            for (int k = 0; k < CIN; k += 4) {
                float4 a[4];
                #pragma unroll
                for (int rr = 0; rr < 4; rr++)
                    a[rr] = *(const float4*)(in_s + (rbase + rr) * CIN + k);
                #pragma unroll
                for (int kk = 0; kk < 4; kk++) {
                    const float wv = Ws[(k + kk) * COUT + lane];
                    #pragma unroll
                    for (int rr = 0; rr < 4; rr++)
                        acc[rr] = fmaf((&a[rr].x)[kk], wv, acc[rr]);
                }
            }
            #pragma unroll
            for (int rr = 0; rr < 4; rr++) vals[rr][0] = acc[rr];
        }

        // Per-row LayerNorm + ReLU + running column max
        #pragma unroll
        for (int rr = 0; rr < 4; rr++) {
            float sum = 0.f, sq = 0.f;
            #pragma unroll
            for (int j = 0; j < PC; j++) { sum += vals[rr][j]; sq += vals[rr][j] * vals[rr][j]; }
            #pragma unroll
            for (int o = 16; o > 0; o >>= 1) {
                sum += __shfl_xor_sync(0xffffffffu, sum, o);
                sq  += __shfl_xor_sync(0xffffffffu, sq,  o);
            }
            const float mu  = sum * (1.0f / COUT);
            const float var = fmaxf(sq * (1.0f / COUT) - mu * mu, 0.f);
            const float inv = rsqrtf(var + 1e-5f);
            #pragma unroll
            for (int j = 0; j < PC; j++) {
                float v = fmaxf(fmaf(gr[j] * (vals[rr][j] - mu), inv, br[j]), 0.f);
                if (!LAST) out_s[(rbase + rr) * COUT + lane * PC + j] = v;
                mx[j] = fmaxf(mx[j], v);
            }
        }
    }
    #pragma unroll
    for (int j = 0; j < PC; j++)
        atomicMax(&aggc[lane * PC + j], __float_as_int(mx[j]));
    __syncthreads();
}

__global__ void __launch_bounds__(256) stage1_kernel(
    const float* __restrict__ data,
    const float* __restrict__ W0, const float* __restrict__ b0,
    const float* __restrict__ g0, const float* __restrict__ be0,
    const float* __restrict__ W1, const float* __restrict__ b1,
    const float* __restrict__ g1, const float* __restrict__ be1,
    const float* __restrict__ W2, const float* __restrict__ b2,
    const float* __restrict__ g2, const float* __restrict__ be2)
{
    extern __shared__ float smem[];
    // Layout (total 12672 floats = 49.5 KB):
    //   bufA : 64*64  (x as 64x32, later h1 64x64)
    //   Ws   : 64*128 (weight tile; upper half doubles as h0 buffer)
    //   aggp/shs/aggc : 3*128
    float* bufA = smem;
    float* Ws   = bufA + 64 * 64;
    float* bufB = Ws + 4096;             // h0 (64x32) aliases Ws[4096..6143]:
                                         // layer1 uses Ws[0..1023], layer2 uses
                                         // Ws[0..2047]; layer3 overwrites after
                                         // h0 is dead (sync-fenced).
    float* aggp = Ws + 64 * 128;
    float* shs  = aggp + 128;
    int*   aggc = (int*)(shs + 128);

    const int tid = threadIdx.x;
    const int blk = blockIdx.x;          // b*NPOLY + p
    const int b = blk >> 8, p = blk & 255;

    // Load x tile (64 x 32), zero channel 31 (vecs[:, :, -1] = 0)
    const float* src = data + (size_t)b * V_TOT * LDIM + LDIM + (size_t)p * VPP * LDIM;
    for (int i = tid; i < 64 * 32; i += 256) {
        float v = src[i];
        if ((i & 31) == 31) v = 0.f;
        bufA[i] = v;
    }
    __syncthreads();

    layer<32, 32,  true,  false>(bufA, bufB, Ws, W0, b0, g0, be0, nullptr, shs, aggc, tid);
    for (int c = tid; c < 32; c += 256) aggp[c] = __int_as_float(aggc[c]);
    __syncthreads();

    layer<32, 64,  false, false>(bufB, bufA, Ws, W1, b1, g1, be1, aggp, shs, aggc, tid);
    for (int c = tid; c < 64; c += 256) aggp[c] = __int_as_float(aggc[c]);
    __syncthreads();

    layer<64, 128, false, true >(bufA, nullptr, Ws, W2, b2, g2, be2, aggp, shs, aggc, tid);

    float* P2 = g_P2 + (size_t)blk * 128;
    for (int c = tid; c < 128; c += 256) P2[c] = __int_as_float(aggc[c]);
}

// ---------------------------------------------------------------------------
// Fold Wq/Wk/Wv:  W_eff[j][c] = W[j][c] + W[j+128][c]   (P = [agg2, agg2])
// ---------------------------------------------------------------------------
__global__ void __launch_bounds__(256) fold_kernel(
    const float* __restrict__ Wq, const float* __restrict__ Wk,
    const float* __restrict__ Wv)
{
    const int i = blockIdx.x * 256 + threadIdx.x;
    if (i >= 128 * 256) return;
    const int j = i >> 8, c = i & 255;
    g_Wq[i] = Wq[j * 256 + c] + Wq[(j + 128) * 256 + c];
    g_Wk[i] = Wk[j * 256 + c] + Wk[(j + 128) * 256 + c];
    g_Wv[i] = Wv[j * 256 + c] + Wv[(j + 128) * 256 + c];
}

// ---------------------------------------------------------------------------
// Stage 2: attention, algebraically reduced. One block per batch.
//   q = P2[b, aid] @ Wq_eff + bq
//   t = Wk_eff @ q            (scores = P2 . t / 16 + const; const cancels)
//   att = softmax(scores)
//   out = (sum_p att_p * P2[b,p]) @ Wv_eff + bv
// ---------------------------------------------------------------------------
__global__ void __launch_bounds__(256) attn_kernel(
    const float* __restrict__ data,
    const float* __restrict__ bq, const float* __restrict__ bk_,
    const float* __restrict__ bv, float* __restrict__ out)
{
    __shared__ float ps[128], qs[256], ts[128], att[256], pbar[128], red[256];
    const int b = blockIdx.x, tid = threadIdx.x;

    const int aid = (int)data[(size_t)b * V_TOT * LDIM];   // data[b][0][0]
    if (tid < 128) ps[tid] = g_P2[((size_t)b * NPOLY + aid) * 128 + tid];
    __syncthreads();

    // q[c]
    {
        float acc = bq[tid];
        #pragma unroll 4
        for (int j = 0; j < 128; j++) acc = fmaf(ps[j], g_Wq[j * 256 + tid], acc);
        qs[tid] = acc;
    }
    __syncthreads();

    // t[j] = sum_c Wk_eff[j][c] * q[c]
    if (tid < 128) {
        float acc = 0.f;
        #pragma unroll 4
        for (int c = 0; c < 256; c++) acc = fmaf(g_Wk[tid * 256 + c], qs[c], acc);
        ts[tid] = acc;
    }
    __syncthreads();

    // scores (per poly p = tid)
    float s = 0.f;
    {
        const float4* Pp = (const float4*)(g_P2 + ((size_t)b * NPOLY + tid) * 128);
        #pragma unroll 8
        for (int j = 0; j < 32; j++) {
            float4 pv = Pp[j];
            s = fmaf(pv.x, ts[4 * j + 0], s);
            s = fmaf(pv.y, ts[4 * j + 1], s);
            s = fmaf(pv.z, ts[4 * j + 2], s);
            s = fmaf(pv.w, ts[4 * j + 3], s);
        }
        s *= 0.0625f;   // 1/sqrt(256)
    }
    // softmax over 256
    red[tid] = s; __syncthreads();
    for (int o = 128; o > 0; o >>= 1) {
        if (tid < o) red[tid] = fmaxf(red[tid], red[tid + o]);
        __syncthreads();
    }
    const float m = red[0]; __syncthreads();
    const float e = expf(s - m);
    red[tid] = e; __syncthreads();
    for (int o = 128; o > 0; o >>= 1) {
        if (tid < o) red[tid] += red[tid + o];
        __syncthreads();
    }
    att[tid] = e / red[0];
    __syncthreads();

    // pbar[j] = sum_p att[p] * P2[b,p,j]   (coalesced across tid=j)
    if (tid < 128) {
        float acc = 0.f;
        const float* Pb = g_P2 + (size_t)b * NPOLY * 128;
        for (int p = 0; p < 256; p++) acc = fmaf(att[p], Pb[p * 128 + tid], acc);
        pbar[tid] = acc;
    }
    __syncthreads();

    // out[c]
    {
        float acc = bv[tid];
        #pragma unroll 4
        for (int j = 0; j < 128; j++) acc = fmaf(pbar[j], g_Wv[j * 256 + tid], acc);
        out[b * 256 + tid] = acc;
    }
}

// ---------------------------------------------------------------------------
extern "C" void kernel_launch(void* const* d_in, const int* in_sizes, int n_in,
                              void* d_out, int out_size)
{
    const float* data = (const float*)d_in[0];
    const float* W0 = (const float*)d_in[1];
    const float* b0 = (const float*)d_in[2];
    const float* g0 = (const float*)d_in[3];
    const float* be0= (const float*)d_in[4];
    const float* W1 = (const float*)d_in[5];
    const float* b1 = (const float*)d_in[6];
    const float* g1 = (const float*)d_in[7];
    const float* be1= (const float*)d_in[8];
    const float* W2 = (const float*)d_in[9];
    const float* b2 = (const float*)d_in[10];
    const float* g2 = (const float*)d_in[11];
    const float* be2= (const float*)d_in[12];
    const float* Wq = (const float*)d_in[13];
    const float* bq = (const float*)d_in[14];
    const float* Wk = (const float*)d_in[15];
    const float* bk = (const float*)d_in[16];
    const float* Wv = (const float*)d_in[17];
    const float* bv = (const float*)d_in[18];
    float* out = (float*)d_out;

    const int smem_bytes = (64*64 + 64*128 + 128 + 128 + 128) * (int)sizeof(float);
    cudaFuncSetAttribute(stage1_kernel,
                         cudaFuncAttributeMaxDynamicSharedMemorySize, smem_bytes);

    stage1_kernel<<<NB * NPOLY, 256, smem_bytes>>>(
        data, W0, b0, g0, be0, W1, b1, g1, be1, W2, b2, g2, be2);
    fold_kernel<<<(128 * 256 + 255) / 256, 256>>>(Wq, Wk, Wv);
    attn_kernel<<<NB, 256>>>(data, bq, bk, bv, out);
}

// round 6
// speedup vs baseline: 1.2318x; 1.0342x over previous
#include <cuda_runtime.h>
#include <cuda_bf16.h>
#include <math.h>

// Problem constants
#define NB     32
#define NPOLY  256
#define VPP    64
#define LDIM   32
#define V_TOT  (1 + NPOLY * VPP)   // 16385 rows per batch in `data`

// Scratch (device globals: no allocations allowed)
__device__ float g_P2[NB * NPOLY * 128];   // agg2 per (b, poly): P = [agg2, agg2]
__device__ float g_Wq[128 * 256];          // folded Wq[:128] + Wq[128:]
__device__ float g_Wk[128 * 256];
__device__ float g_Wv[128 * 256];

// ---- packed f32x2 helpers (sm_103a dual-fp32 pipe; PTX-only) -------------
__device__ __forceinline__ unsigned long long pack2(float x, float y) {
    unsigned long long r;
    asm("mov.b64 %0, {%1, %2};" : "=l"(r) : "f"(x), "f"(y));
    return r;
}
__device__ __forceinline__ unsigned long long ffma2(unsigned long long a,
                                                    unsigned long long b,
                                                    unsigned long long c) {
    unsigned long long d;
    asm("fma.rn.f32x2 %0, %1, %2, %3;" : "=l"(d) : "l"(a), "l"(b), "l"(c));
    return d;
}
__device__ __forceinline__ float2 unpack2(unsigned long long v) {
    float2 f;
    asm("mov.b64 {%0, %1}, %2;" : "=f"(f.x), "=f"(f.y) : "l"(v));
    return f;
}

// ---------------------------------------------------------------------------
// Stage 1: per (b, poly) block — 3 x (GEMM + LayerNorm + ReLU + column max).
// x = concat([h, broadcast(agg)]) => per-row GEMM uses only the top CIN rows
// of W; the agg part folds into a per-block shared term. Only agg2 (128) is
// emitted: P = concat([agg2, agg2]).
// 8-row register blocking per warp: weights for a 4-k group are loaded ONCE
// (LDS.128) and reused across 8 rows -> halves crossbar traffic vs 4-row.
// ---------------------------------------------------------------------------
template<int CIN, int COUT, bool FIRST, bool LAST>
__device__ __forceinline__ void layer(
    const float* __restrict__ in_s,   // 64 x CIN (smem)
    float*       __restrict__ out_s,  // 64 x COUT (smem) or unused if LAST
    float*       __restrict__ Ws,     // smem weight buffer (CIN x COUT floats)
    const float* __restrict__ W,      // global weights ((CIN or 2*CIN) x COUT)
    const float* __restrict__ bias,
    const float* __restrict__ g,
    const float* __restrict__ beta,
    const float* __restrict__ aggp,   // previous agg (CIN) or unused if FIRST
    float*       __restrict__ shs,    // smem shared-term (COUT)
    int*         __restrict__ aggc,   // smem column max (COUT), float bits as int
    int tid)
{
    constexpr int PC = COUT / 32;     // columns per lane (1, 2, or 4)
    const int warp = tid >> 5, lane = tid & 31;
    const int rbase = warp * 8;       // this warp's 8 rows

    // Stage varying-part weights W[0:CIN][0:COUT] (contiguous, vectorized)
    for (int i = tid; i < CIN * COUT / 4; i += 256)
        ((float4*)Ws)[i] = ((const float4*)W)[i];

    // Shared term: bias + agg_prev @ W[CIN:2*CIN]
    for (int c = tid; c < COUT; c += 256) {
        float s = bias[c];
        if (!FIRST) {
            #pragma unroll 4
            for (int k = 0; k < CIN; k++)
                s = fmaf(aggp[k], W[(CIN + k) * COUT + c], s);
        }
        shs[c]  = s;
        aggc[c] = 0;   // relu output >= 0: float bits monotone as int
    }
    __syncthreads();

    float gr[PC], br[PC], mx[PC];
    #pragma unroll
    for (int j = 0; j < PC; j++) {
        const int c = lane * PC + j;
        gr[j] = g[c]; br[j] = beta[c]; mx[j] = 0.f;
    }

    float vals[8][PC];   // post-GEMM values

    if constexpr (PC == 4) {
        unsigned long long acc[8][2];
        {
            const ulonglong2 s0 = *(const ulonglong2*)(shs + lane * 4);
            #pragma unroll
            for (int r = 0; r < 8; r++) { acc[r][0] = s0.x; acc[r][1] = s0.y; }
        }
        for (int k0 = 0; k0 < CIN; k0 += 4) {
            unsigned long long w[4][2];
            #pragma unroll
            for (int kk = 0; kk < 4; kk++) {
                const ulonglong2 wv =
                    *(const ulonglong2*)(Ws + (k0 + kk) * COUT + lane * 4);
                w[kk][0] = wv.x; w[kk][1] = wv.y;
            }
            #pragma unroll
            for (int r = 0; r < 8; r++) {
                const float4 a = *(const float4*)(in_s + (rbase + r) * CIN + k0);
                unsigned long long ap;
                ap = pack2(a.x, a.x);
                acc[r][0] = ffma2(ap, w[0][0], acc[r][0]);
                acc[r][1] = ffma2(ap, w[0][1], acc[r][1]);
                ap = pack2(a.y, a.y);
                acc[r][0] = ffma2(ap, w[1][0], acc[r][0]);
                acc[r][1] = ffma2(ap, w[1][1], acc[r][1]);
                ap = pack2(a.z, a.z);
                acc[r][0] = ffma2(ap, w[2][0], acc[r][0]);
                acc[r][1] = ffma2(ap, w[2][1], acc[r][1]);
                ap = pack2(a.w, a.w);
                acc[r][0] = ffma2(ap, w[3][0], acc[r][0]);
                acc[r][1] = ffma2(ap, w[3][1], acc[r][1]);
            }
        }
        #pragma unroll
        for (int r = 0; r < 8; r++) {
            const float2 f0 = unpack2(acc[r][0]), f1 = unpack2(acc[r][1]);
            vals[r][0] = f0.x; vals[r][1] = f0.y; vals[r][2] = f1.x; vals[r][3] = f1.y;
        }
    } else if constexpr (PC == 2) {
        unsigned long long acc[8];
        {
            const unsigned long long s0 = *(const unsigned long long*)(shs + lane * 2);
            #pragma unroll
            for (int r = 0; r < 8; r++) acc[r] = s0;
        }
        for (int k0 = 0; k0 < CIN; k0 += 4) {
            unsigned long long w[4];
            #pragma unroll
            for (int kk = 0; kk < 4; kk++)
                w[kk] = *(const unsigned long long*)(Ws + (k0 + kk) * COUT + lane * 2);
            #pragma unroll
            for (int r = 0; r < 8; r++) {
                const float4 a = *(const float4*)(in_s + (rbase + r) * CIN + k0);
                acc[r] = ffma2(pack2(a.x, a.x), w[0], acc[r]);
                acc[r] = ffma2(pack2(a.y, a.y), w[1], acc[r]);
                acc[r] = ffma2(pack2(a.z, a.z), w[2], acc[r]);
                acc[r] = ffma2(pack2(a.w, a.w), w[3], acc[r]);
            }
        }
        #pragma unroll
        for (int r = 0; r < 8; r++) {
            const float2 f = unpack2(acc[r]);
            vals[r][0] = f.x; vals[r][1] = f.y;
        }
    } else {
        float acc[8];
        #pragma unroll
        for (int r = 0; r < 8; r++) acc[r] = shs[lane];
        for (int k0 = 0; k0 < CIN; k0 += 4) {
            float w[4];
            #pragma unroll
            for (int kk = 0; kk < 4; kk++)
                w[kk] = Ws[(k0 + kk) * COUT + lane];
            #pragma unroll
            for (int r = 0; r < 8; r++) {
                const float4 a = *(const float4*)(in_s + (rbase + r) * CIN + k0);
                acc[r] = fmaf(a.x, w[0], acc[r]);
                acc[r] = fmaf(a.y, w[1], acc[r]);
                acc[r] = fmaf(a.z, w[2], acc[r]);
                acc[r] = fmaf(a.w, w[3], acc[r]);
            }
        }
        #pragma unroll
        for (int r = 0; r < 8; r++) vals[r][0] = acc[r];
    }

    // Per-row LayerNorm + ReLU + running column max
    #pragma unroll
    for (int r = 0; r < 8; r++) {
        float sum = 0.f, sq = 0.f;
        #pragma unroll
        for (int j = 0; j < PC; j++) { sum += vals[r][j]; sq += vals[r][j] * vals[r][j]; }
        #pragma unroll
        for (int o = 16; o > 0; o >>= 1) {
            sum += __shfl_xor_sync(0xffffffffu, sum, o);
            sq  += __shfl_xor_sync(0xffffffffu, sq,  o);
        }
        const float mu  = sum * (1.0f / COUT);
        const float var = fmaxf(sq * (1.0f / COUT) - mu * mu, 0.f);
        const float inv = rsqrtf(var + 1e-5f);
        float v[PC];
        #pragma unroll
        for (int j = 0; j < PC; j++) {
            v[j] = fmaxf(fmaf(gr[j] * (vals[r][j] - mu), inv, br[j]), 0.f);
            mx[j] = fmaxf(mx[j], v[j]);
        }
        if (!LAST) {
            if constexpr (PC == 4)
                *(float4*)(out_s + (rbase + r) * COUT + lane * 4) =
                    make_float4(v[0], v[1], v[2], v[3]);
            else if constexpr (PC == 2)
                *(float2*)(out_s + (rbase + r) * COUT + lane * 2) =
                    make_float2(v[0], v[1]);
            else
                out_s[(rbase + r) * COUT + lane] = v[0];
        }
    }
    #pragma unroll
    for (int j = 0; j < PC; j++)
        atomicMax(&aggc[lane * PC + j], __float_as_int(mx[j]));
    __syncthreads();
}

__global__ void __launch_bounds__(256, 3) stage1_kernel(
    const float* __restrict__ data,
    const float* __restrict__ W0, const float* __restrict__ b0,
    const float* __restrict__ g0, const float* __restrict__ be0,
    const float* __restrict__ W1, const float* __restrict__ b1,
    const float* __restrict__ g1, const float* __restrict__ be1,
    const float* __restrict__ W2, const float* __restrict__ b2,
    const float* __restrict__ g2, const float* __restrict__ be2)
{
    extern __shared__ float smem[];
    // Layout (total 12672 floats = 49.5 KB):
    //   bufA : 64*64  (x as 64x32, later h1 64x64)
    //   Ws   : 64*128 (weight tile; upper half doubles as h0 buffer)
    //   aggp/shs/aggc : 3*128
    float* bufA = smem;
    float* Ws   = bufA + 64 * 64;
    float* bufB = Ws + 4096;             // h0 (64x32) aliases Ws[4096..6143]:
                                         // layer1 uses Ws[0..1023], layer2 uses
                                         // Ws[0..2047]; layer3 overwrites after
                                         // h0 is dead (sync-fenced).
    float* aggp = Ws + 64 * 128;
    float* shs  = aggp + 128;
    int*   aggc = (int*)(shs + 128);

    const int tid = threadIdx.x;
    const int blk = blockIdx.x;          // b*NPOLY + p
    const int b = blk >> 8, p = blk & 255;

    // Load x tile (64 x 32), zero channel 31 (vecs[:, :, -1] = 0)
    const float* src = data + (size_t)b * V_TOT * LDIM + LDIM + (size_t)p * VPP * LDIM;
    for (int i = tid; i < 64 * 32; i += 256) {
        float v = src[i];
        if ((i & 31) == 31) v = 0.f;
        bufA[i] = v;
    }
    __syncthreads();

    layer<32, 32,  true,  false>(bufA, bufB, Ws, W0, b0, g0, be0, nullptr, shs, aggc, tid);
    for (int c = tid; c < 32; c += 256) aggp[c] = __int_as_float(aggc[c]);
    __syncthreads();

    layer<32, 64,  false, false>(bufB, bufA, Ws, W1, b1, g1, be1, aggp, shs, aggc, tid);
    for (int c = tid; c < 64; c += 256) aggp[c] = __int_as_float(aggc[c]);
    __syncthreads();

    layer<64, 128, false, true >(bufA, nullptr, Ws, W2, b2, g2, be2, aggp, shs, aggc, tid);

    float* P2 = g_P2 + (size_t)blk * 128;
    for (int c = tid; c < 128; c += 256) P2[c] = __int_as_float(aggc[c]);
}

// ---------------------------------------------------------------------------
// Fold Wq/Wk/Wv:  W_eff[j][c] = W[j][c] + W[j+128][c]   (P = [agg2, agg2])
// ---------------------------------------------------------------------------
__global__ void __launch_bounds__(256) fold_kernel(
    const float* __restrict__ Wq, const float* __restrict__ Wk,
    const float* __restrict__ Wv)
{
    const int i = blockIdx.x * 256 + threadIdx.x;
    if (i >= 128 * 256) return;
    const int j = i >> 8, c = i & 255;
    g_Wq[i] = Wq[j * 256 + c] + Wq[(j + 128) * 256 + c];
    g_Wk[i] = Wk[j * 256 + c] + Wk[(j + 128) * 256 + c];
    g_Wv[i] = Wv[j * 256 + c] + Wv[(j + 128) * 256 + c];
}

// ---------------------------------------------------------------------------
// Stage 2: attention, algebraically reduced. One block per batch.
//   q = P2[b, aid] @ Wq_eff + bq
//   t = Wk_eff @ q            (scores = P2 . t / 16 + const; const cancels)
//   att = softmax(scores)
//   out = (sum_p att_p * P2[b,p]) @ Wv_eff + bv
// ---------------------------------------------------------------------------
__global__ void __launch_bounds__(256) attn_kernel(
    const float* __restrict__ data,
    const float* __restrict__ bq, const float* __restrict__ bk_,
    const float* __restrict__ bv, float* __restrict__ out)
{
    __shared__ float ps[128], qs[256], ts[128], att[256], pbar[128], red[256];
    const int b = blockIdx.x, tid = threadIdx.x;

    const int aid = (int)data[(size_t)b * V_TOT * LDIM];   // data[b][0][0]
    if (tid < 128) ps[tid] = g_P2[((size_t)b * NPOLY + aid) * 128 + tid];
    __syncthreads();

    // q[c]
    {
        float acc = bq[tid];
        #pragma unroll 4
        for (int j = 0; j < 128; j++) acc = fmaf(ps[j], g_Wq[j * 256 + tid], acc);
        qs[tid] = acc;
    }
    __syncthreads();

    // t[j] = sum_c Wk_eff[j][c] * q[c]
    if (tid < 128) {
        float acc = 0.f;
        #pragma unroll 4
        for (int c = 0; c < 256; c++) acc = fmaf(g_Wk[tid * 256 + c], qs[c], acc);
        ts[tid] = acc;
    }
    __syncthreads();

    // scores (per poly p = tid)
    float s = 0.f;
    {
        const float4* Pp = (const float4*)(g_P2 + ((size_t)b * NPOLY + tid) * 128);
        #pragma unroll 8
        for (int j = 0; j < 32; j++) {
            float4 pv = Pp[j];
            s = fmaf(pv.x, ts[4 * j + 0], s);
            s = fmaf(pv.y, ts[4 * j + 1], s);
            s = fmaf(pv.z, ts[4 * j + 2], s);
            s = fmaf(pv.w, ts[4 * j + 3], s);
        }
        s *= 0.0625f;   // 1/sqrt(256)
    }
    // softmax over 256
    red[tid] = s; __syncthreads();
    for (int o = 128; o > 0; o >>= 1) {
        if (tid < o) red[tid] = fmaxf(red[tid], red[tid + o]);
        __syncthreads();
    }
    const float m = red[0]; __syncthreads();
    const float e = expf(s - m);
    red[tid] = e; __syncthreads();
    for (int o = 128; o > 0; o >>= 1) {
        if (tid < o) red[tid] += red[tid + o];
        __syncthreads();
    }
    att[tid] = e / red[0];
    __syncthreads();

    // pbar[j] = sum_p att[p] * P2[b,p,j]   (coalesced across tid=j)
    if (tid < 128) {
        float acc = 0.f;
        const float* Pb = g_P2 + (size_t)b * NPOLY * 128;
        for (int p = 0; p < 256; p++) acc = fmaf(att[p], Pb[p * 128 + tid], acc);
        pbar[tid] = acc;
    }
    __syncthreads();

    // out[c]
    {
        float acc = bv[tid];
        #pragma unroll 4
        for (int j = 0; j < 128; j++) acc = fmaf(pbar[j], g_Wv[j * 256 + tid], acc);
        out[b * 256 + tid] = acc;
    }
}

// ---------------------------------------------------------------------------
extern "C" void kernel_launch(void* const* d_in, const int* in_sizes, int n_in,
                              void* d_out, int out_size)
{
    const float* data = (const float*)d_in[0];
    const float* W0 = (const float*)d_in[1];
    const float* b0 = (const float*)d_in[2];
    const float* g0 = (const float*)d_in[3];
    const float* be0= (const float*)d_in[4];
    const float* W1 = (const float*)d_in[5];
    const float* b1 = (const float*)d_in[6];
    const float* g1 = (const float*)d_in[7];
    const float* be1= (const float*)d_in[8];
    const float* W2 = (const float*)d_in[9];
    const float* b2 = (const float*)d_in[10];
    const float* g2 = (const float*)d_in[11];
    const float* be2= (const float*)d_in[12];
    const float* Wq = (const float*)d_in[13];
    const float* bq = (const float*)d_in[14];
    const float* Wk = (const float*)d_in[15];
    const float* bk = (const float*)d_in[16];
    const float* Wv = (const float*)d_in[17];
    const float* bv = (const float*)d_in[18];
    float* out = (float*)d_out;

    const int smem_bytes = (64*64 + 64*128 + 128 + 128 + 128) * (int)sizeof(float);
    cudaFuncSetAttribute(stage1_kernel,
                         cudaFuncAttributeMaxDynamicSharedMemorySize, smem_bytes);

    stage1_kernel<<<NB * NPOLY, 256, smem_bytes>>>(
        data, W0, b0, g0, be0, W1, b1, g1, be1, W2, b2, g2, be2);
    fold_kernel<<<(128 * 256 + 255) / 256, 256>>>(Wq, Wk, Wv);
    attn_kernel<<<NB, 256>>>(data, bq, bk, bv, out);
}